// round 17
// baseline (speedup 1.0000x reference)
#include <cuda_runtime.h>
#include <math.h>

#define NB 32
#define NS 48000
#define L_CHUNK 64
#define NCH (NS / L_CHUNK)      /* 750 */
#define NPAIR (NCH / 2)         /* 375 */
#define PLANE (NS * NB)

// Per-sample mix-folded output row: y = ga.s0123 + gb.xy.s45 + gb.z
__device__ float4 g_ga[(size_t)PLANE];
__device__ float4 g_gb[(size_t)PLANE];
// Per (chunk, lane) affine map: 30 floats, [c][b][30]
__device__ float g_maps[(size_t)NCH * NB * 30];
// Inclusive chunk-end states: 6 planes of [c][b]
__device__ float g_state[6 * (size_t)NCH * NB];

// shelf constants
#define CW_L  0.9994645875f     /* cos(2pi*250/48000) */
#define ALC_L 0.0231360485f     /* sin(w0_l)*sqrt(2)/2 */
#define CW_H  0.8660254038f     /* cos(pi/6) */
#define ALC_H 0.3535533906f     /* sin(pi/6)*sqrt(2)/2 */
#define KDB   0.0830482024f     /* log2(10)/40 */

// ---------------- fast approx helpers ----------------
__device__ __forceinline__ float f_tanh(float x) {
    float r; asm("tanh.approx.f32 %0, %1;" : "=f"(r) : "f"(x)); return r;
}
__device__ __forceinline__ float f_rcp(float x) {
    float r; asm("rcp.approx.f32 %0, %1;" : "=f"(r) : "f"(x)); return r;
}
__device__ __forceinline__ float f_ex2(float x) {
    float r; asm("ex2.approx.f32 %0, %1;" : "=f"(r) : "f"(x)); return r;
}

// ---------------------------------------------------------------------------
// Coefficient reconstruction: pure FMA/MUL (reciprocals precomputed).
// ---------------------------------------------------------------------------
__device__ __forceinline__ void make_coefs(const float4& pa, const float4& pb, float c[15])
{
    {   // low shelf: pa.x = sA, pa.y = 1/a0
        float sA = pa.x, inv = pa.y;
        float A  = sA * sA;
        float t  = 2.0f * sA * ALC_L;
        float ap = A + 1.0f, am = A - 1.0f;
        c[0] = A * (ap - am * CW_L + t) * inv;
        c[1] = 2.0f * A * (am - ap * CW_L) * inv;
        c[2] = A * (ap - am * CW_L - t) * inv;
        c[3] = -2.0f * (am + ap * CW_L) * inv;
        c[4] = (ap + am * CW_L - t) * inv;
    }
    {   // mid peaking: pb = (cw, alA, alrA, 1/a0)
        float cw = pb.x, alA = pb.y, alrA = pb.z, inv = pb.w;
        c[5] = (1.0f + alA) * inv;
        c[6] = -2.0f * cw * inv;
        c[7] = (1.0f - alA) * inv;
        c[8] = c[6];
        c[9] = (1.0f - alrA) * inv;
    }
    {   // high shelf: pa.z = sA, pa.w = 1/a0
        float sA = pa.z, inv = pa.w;
        float A  = sA * sA;
        float t  = 2.0f * sA * ALC_H;
        float ap = A + 1.0f, am = A - 1.0f;
        c[10] = A * (ap + am * CW_H + t) * inv;
        c[11] = -2.0f * A * (am + ap * CW_H) * inv;
        c[12] = A * (ap + am * CW_H - t) * inv;
        c[13] = 2.0f * (am - ap * CW_H) * inv;
        c[14] = (ap - am * CW_H - t) * inv;
    }
}

// ---------------------------------------------------------------------------
// Step primitives on coefficient array c[15]; each returns the tone-stack
// output y3 (the output-row component).
// ---------------------------------------------------------------------------
__device__ __forceinline__ float stepF(const float c[15], float u[6], float v)
{
    float y1 = fmaf(c[0], v, u[0]);
    float a  = fmaf(c[1], v, fmaf(-c[3], y1, u[1]));
    float bb = fmaf(c[2], v, -c[4] * y1);
    float y2 = fmaf(c[5], y1, u[2]);
    float cc = fmaf(c[6], y1, fmaf(-c[8], y2, u[3]));
    float dd = fmaf(c[7], y1, -c[9] * y2);
    float y3 = fmaf(c[10], y2, u[4]);
    float ee = fmaf(c[11], y2, fmaf(-c[13], y3, u[5]));
    float ff = fmaf(c[12], y2, -c[14] * y3);
    u[0]=a; u[1]=bb; u[2]=cc; u[3]=dd; u[4]=ee; u[5]=ff;
    return y3;
}
__device__ __forceinline__ float stepM(const float c[15], float w[4])
{
    float y2 = w[0];
    float a  = fmaf(-c[8], y2, w[1]);
    float bb = -c[9] * y2;
    float y3 = fmaf(c[10], y2, w[2]);
    float cc = fmaf(c[11], y2, fmaf(-c[13], y3, w[3]));
    float dd = fmaf(c[12], y2, -c[14] * y3);
    w[0]=a; w[1]=bb; w[2]=cc; w[3]=dd;
    return y3;
}
__device__ __forceinline__ float stepH(const float c[15], float w[2])
{
    float y3 = w[0];
    float a  = fmaf(-c[13], y3, w[1]);
    float bb = -c[14] * y3;
    w[0]=a; w[1]=bb;
    return y3;
}

// ---------------------------------------------------------------------------
// FUSED prep+map: one block (2 warps) per 64-sample chunk, lane = batch row.
//   warp 0 (producer): stage raw inputs coalesced -> transcendental param
//                      compute -> pa/pb/sv/mix into smem.
//   warp 1 (consumer): read params from smem -> coefs -> 7 column pushes ->
//                      per-sample output rows (g_ga/g_gb) + chunk map record.
// Phases alternate per 16-sample quarter via block-level __syncthreads.
// ---------------------------------------------------------------------------
#define QS 16                   /* samples per quarter */

__global__ void __launch_bounds__(64) fused_kernel(
        const float* __restrict__ x,
        const float* __restrict__ alpha,
        const float* __restrict__ beta,
        const float* __restrict__ low_db,
        const float* __restrict__ mid_db,
        const float* __restrict__ mid_fc,
        const float* __restrict__ mid_Q,
        const float* __restrict__ high_db,
        const float* __restrict__ alpha_a)
{
    __shared__ float  sX[80 * 33];        // x[n0-8 .. n0+71], [i][b] stride 33
    __shared__ float4 sA4[QS * 33];       // raw(al,be,low,mid) -> pa
    __shared__ float4 sB4[QS * 33];       // raw(fc,Q,high,aa)  -> pb
    __shared__ float  sC[3][QS * 33];     // sv, my(=aa*ya), z(=1-aa)

    const int c    = blockIdx.x;
    const int tid  = threadIdx.x;
    const int wid  = tid >> 5;
    const int lane = tid & 31;
    const int n0   = c * L_CHUNK;

    // ---- stage x window (both warps; coalesced along n) ----
    for (int it = 0; it < 10; ++it) {
        int li = it * 64 + tid;           // 0..639
        int b  = li / 20;
        int f4 = li % 20;
        int g  = n0 - 8 + 4 * f4;
        const float* xb = x + (size_t)b * NS;
        float4 v;
        if (g >= 0 && g + 3 < NS) {
            v = *(const float4*)(xb + g);
        } else {
            v.x = (g + 0 >= 0 && g + 0 < NS) ? xb[g + 0] : 0.0f;
            v.y = (g + 1 >= 0 && g + 1 < NS) ? xb[g + 1] : 0.0f;
            v.z = (g + 2 >= 0 && g + 2 < NS) ? xb[g + 2] : 0.0f;
            v.w = (g + 3 >= 0 && g + 3 < NS) ? xb[g + 3] : 0.0f;
        }
        sX[(4 * f4 + 0) * 33 + b] = v.x;
        sX[(4 * f4 + 1) * 33 + b] = v.y;
        sX[(4 * f4 + 2) * 33 + b] = v.z;
        sX[(4 * f4 + 3) * 33 + b] = v.w;
    }
    __syncthreads();

    // producer state: 15-tap running window sum for sample n0
    float W = 0.0f;
    if (wid == 0) {
        #pragma unroll
        for (int i = 1; i <= 15; ++i) W += fabsf(sX[i * 33 + lane]);
    }

    // consumer state: affine-map accumulators
    float u1[6] = {1,0,0,0,0,0};
    float u2[6] = {0,1,0,0,0,0};
    float u3[4] = {1,0,0,0};
    float u4[4] = {0,1,0,0};
    float u5[2] = {1,0};
    float u6[2] = {0,1};
    float dd[6] = {0,0,0,0,0,0};

    float* sAf = (float*)sA4;
    float* sBf = (float*)sB4;

    for (int q = 0; q < 4; ++q) {
        const int jq0 = q * QS;           // chunk-local first sample

        // ==== PRODUCER phase ====
        if (wid == 0) {
            // stage 8 raw arrays for this quarter (coalesced lines):
            // 4 iters x (8 rows x 4 float4) covers 32 rows x 16 floats
            const int b  = (lane >> 2);   // row offset within group of 8
            const int f4 = lane & 3;      // float4 index within quarter row
            #pragma unroll
            for (int it = 0; it < 4; ++it) {
                int row = 8 * it + b;
                size_t src = (size_t)row * NS + n0 + jq0 + 4 * f4;
                float4 vA0 = *(const float4*)(alpha   + src);
                float4 vA1 = *(const float4*)(beta    + src);
                float4 vA2 = *(const float4*)(low_db  + src);
                float4 vA3 = *(const float4*)(mid_db  + src);
                float4 vB0 = *(const float4*)(mid_fc  + src);
                float4 vB1 = *(const float4*)(mid_Q   + src);
                float4 vB2 = *(const float4*)(high_db + src);
                float4 vB3 = *(const float4*)(alpha_a + src);
                #pragma unroll
                for (int i = 0; i < 4; ++i) {
                    int base = ((4 * f4 + i) * 33 + row) * 4;
                    sAf[base + 0] = ((const float*)&vA0)[i];
                    sAf[base + 1] = ((const float*)&vA1)[i];
                    sAf[base + 2] = ((const float*)&vA2)[i];
                    sAf[base + 3] = ((const float*)&vA3)[i];
                    sBf[base + 0] = ((const float*)&vB0)[i];
                    sBf[base + 1] = ((const float*)&vB1)[i];
                    sBf[base + 2] = ((const float*)&vB2)[i];
                    sBf[base + 3] = ((const float*)&vB3)[i];
                }
            }
            __syncwarp();

            // param compute (lane = batch row), in-place overwrite
            #pragma unroll 4
            for (int j = 0; j < QS; ++j) {
                const int jc = jq0 + j;
                float4 ra = sA4[j * 33 + lane];   // alpha,beta,low_db,mid_db
                float4 rb = sB4[j * 33 + lane];   // fc,Q,high_db,alpha_a
                float xv  = sX[(jc + 8) * 33 + lane];

                float env = W * (1.0f / 15.0f);
                W += fabsf(sX[(jc + 16) * 33 + lane]) - fabsf(sX[(jc + 1) * 33 + lane]);

                float xa = fabsf(xv);
                float gate = fmaf(0.5f, f_tanh(4.0f * (xa - env)), 0.5f);
                float av = gate * xv;
                float sv = (1.0f - gate) * xv;
                float ya = f_tanh(fmaf(ra.x, av, ra.y)) - f_tanh(ra.y);

                float sA_l = f_ex2(ra.z * (0.5f * KDB));
                float sA_h = f_ex2(rb.z * (0.5f * KDB));
                float invL, invH;
                {
                    float A = sA_l * sA_l, t = 2.0f * sA_l * ALC_L;
                    invL = f_rcp((A + 1.0f) + (A - 1.0f) * CW_L + t);
                }
                {
                    float A = sA_h * sA_h, t = 2.0f * sA_h * ALC_H;
                    invH = f_rcp((A + 1.0f) - (A - 1.0f) * CW_H + t);
                }
                float A_m = f_ex2(ra.w * KDB);
                float w0  = rb.x * 1.30899693e-4f;   // 2*pi/48000
                float sw = __sinf(w0), cw = __cosf(w0);
                float alq  = sw * 0.5f * f_rcp(rb.y);
                float alA  = alq * A_m;
                float alrA = alq * f_rcp(A_m);
                float invM = f_rcp(1.0f + alrA);
                float aav  = rb.w;

                sA4[j * 33 + lane] = make_float4(sA_l, invL, sA_h, invH);
                sB4[j * 33 + lane] = make_float4(cw, alA, alrA, invM);
                sC[0][j * 33 + lane] = sv;
                sC[1][j * 33 + lane] = aav * ya;
                sC[2][j * 33 + lane] = 1.0f - aav;
            }
        }
        __syncthreads();

        // ==== CONSUMER phase ====
        if (wid == 1) {
            #pragma unroll 4
            for (int j = 0; j < QS; ++j) {
                const int jc = jq0 + j;
                float4 pa = sA4[j * 33 + lane];
                float4 pb = sB4[j * 33 + lane];
                float sv = sC[0][j * 33 + lane];
                float my = sC[1][j * 33 + lane];
                float z  = sC[2][j * 33 + lane];

                float cf[15];
                make_coefs(pa, pb, cf);

                float g1 = stepF(cf, u1, 0.0f);
                float g2 = stepF(cf, u2, 0.0f);
                float g3 = stepM(cf, u3);
                float g4 = stepM(cf, u4);
                float g5 = stepH(cf, u5);
                float g6 = stepH(cf, u6);
                float hy = stepF(cf, dd, sv);

                int oc = (n0 + jc) * NB + lane;
                g_ga[oc] = make_float4(z * g1, z * g2, z * g3, z * g4);
                g_gb[oc] = make_float4(z * g5, z * g6, fmaf(z, hy, my), 0.0f);
            }
        }
        __syncthreads();
    }

    if (wid == 1) {
        float* rec = g_maps + (size_t)(c * NB + lane) * 30;
        #pragma unroll
        for (int k = 0; k < 6; ++k) rec[k]      = u1[k];
        #pragma unroll
        for (int k = 0; k < 6; ++k) rec[6 + k]  = u2[k];
        #pragma unroll
        for (int k = 0; k < 4; ++k) rec[12 + k] = u3[k];
        #pragma unroll
        for (int k = 0; k < 4; ++k) rec[16 + k] = u4[k];
        rec[20] = u5[0]; rec[21] = u5[1];
        rec[22] = u6[0]; rec[23] = u6[1];
        #pragma unroll
        for (int k = 0; k < 6; ++k) rec[24 + k] = dd[k];
    }
}

// ---------------------------------------------------------------------------
// Map compose helpers (block-lower-triangular sparsity).
// ---------------------------------------------------------------------------
__device__ __forceinline__ void bmv_full(const float* B, const float* w, float* r)
{
    r[0] = w[0]*B[0] + w[1]*B[6];
    r[1] = w[0]*B[1] + w[1]*B[7];
    r[2] = w[0]*B[2] + w[1]*B[8]  + w[2]*B[12] + w[3]*B[16];
    r[3] = w[0]*B[3] + w[1]*B[9]  + w[2]*B[13] + w[3]*B[17];
    r[4] = w[0]*B[4] + w[1]*B[10] + w[2]*B[14] + w[3]*B[18] + w[4]*B[20] + w[5]*B[22];
    r[5] = w[0]*B[5] + w[1]*B[11] + w[2]*B[15] + w[3]*B[19] + w[4]*B[21] + w[5]*B[23];
}
__device__ __forceinline__ void bmv_mid(const float* B, const float* w, float* r)
{
    r[0] = w[0]*B[12] + w[1]*B[16];
    r[1] = w[0]*B[13] + w[1]*B[17];
    r[2] = w[0]*B[14] + w[1]*B[18] + w[2]*B[20] + w[3]*B[22];
    r[3] = w[0]*B[15] + w[1]*B[19] + w[2]*B[21] + w[3]*B[23];
}
__device__ __forceinline__ void bmv_high(const float* B, const float* w, float* r)
{
    r[0] = w[0]*B[20] + w[1]*B[22];
    r[1] = w[0]*B[21] + w[1]*B[23];
}
// C = B after A  (A applied first)
__device__ __forceinline__ void compose(const float* A, const float* B, float* C)
{
    bmv_full(B, A + 0,  C + 0);
    bmv_full(B, A + 6,  C + 6);
    bmv_mid (B, A + 12, C + 12);
    bmv_mid (B, A + 16, C + 16);
    bmv_high(B, A + 20, C + 20);
    bmv_high(B, A + 22, C + 22);
    float t6[6];
    bmv_full(B, A + 24, t6);
    #pragma unroll
    for (int k = 0; k < 6; ++k) C[24 + k] = t6[k] + B[24 + k];
}

// ---------------------------------------------------------------------------
// Scan: one block per batch lane. Pair-compose in registers, Hillis-Steele
// over 375 pairs in smem, emit both chunk-end states.
// ---------------------------------------------------------------------------
__global__ void __launch_bounds__(384) scan_kernel()
{
    __shared__ float sm[NPAIR * 30];    // 45000 B
    const int t = threadIdx.x;
    const int b = blockIdx.x;
    const bool on = (t < NPAIR);

    float A[30];
    if (on) {
        const float* srcA = g_maps + (size_t)((2 * t)     * NB + b) * 30;
        const float* srcB = g_maps + (size_t)((2 * t + 1) * NB + b) * 30;
        float Bm[30], P[30];
        #pragma unroll
        for (int k = 0; k < 30; ++k) A[k]  = srcA[k];
        #pragma unroll
        for (int k = 0; k < 30; ++k) Bm[k] = srcB[k];
        compose(A, Bm, P);
        #pragma unroll
        for (int k = 0; k < 30; ++k) sm[t * 30 + k] = P[k];
    }
    __syncthreads();

    for (int off = 1; off < NPAIR; off <<= 1) {
        float Ap[30], Bp[30];
        const bool act = on && (t >= off);
        if (act) {
            #pragma unroll
            for (int k = 0; k < 30; ++k) Ap[k] = sm[(t - off) * 30 + k];
            #pragma unroll
            for (int k = 0; k < 30; ++k) Bp[k] = sm[t * 30 + k];
        }
        __syncthreads();
        if (act) {
            float C[30];
            compose(Ap, Bp, C);
            #pragma unroll
            for (int k = 0; k < 30; ++k) sm[t * 30 + k] = C[k];
        }
        __syncthreads();
    }

    if (on) {
        #pragma unroll
        for (int k = 0; k < 6; ++k)
            g_state[(size_t)k * (NCH * NB) + (2 * t + 1) * NB + b] = sm[t * 30 + 24 + k];
        float se[6];
        if (t == 0) {
            #pragma unroll
            for (int k = 0; k < 6; ++k) se[k] = A[24 + k];
        } else {
            float w[6];
            #pragma unroll
            for (int k = 0; k < 6; ++k) w[k] = sm[(t - 1) * 30 + 24 + k];
            bmv_full(A, w, se);
            #pragma unroll
            for (int k = 0; k < 6; ++k) se[k] += A[24 + k];
        }
        #pragma unroll
        for (int k = 0; k < 6; ++k)
            g_state[(size_t)k * (NCH * NB) + (2 * t) * NB + b] = se[k];
    }
}

// ---------------------------------------------------------------------------
// Pass 2 (PARALLEL): y[b][n] = ga . s0[0:4] + gb.xy . s0[4:6] + gb.z
// ---------------------------------------------------------------------------
__global__ void __launch_bounds__(1024) out_kernel(float* __restrict__ out)
{
    __shared__ float buf[32 * 33];

    const int tx = threadIdx.x;     // batch lane
    const int ty = threadIdx.y;     // sample within tile
    const int n  = blockIdx.x * 32 + ty;
    const int c  = n / L_CHUNK;

    const int ofs = n * NB + tx;
    float4 ga = g_ga[ofs];
    float4 gb = g_gb[ofs];

    float y = gb.z;
    if (c > 0) {
        const size_t sb = (size_t)(c - 1) * NB + tx;
        y = fmaf(ga.x, g_state[0 * (size_t)(NCH * NB) + sb],
            fmaf(ga.y, g_state[1 * (size_t)(NCH * NB) + sb],
            fmaf(ga.z, g_state[2 * (size_t)(NCH * NB) + sb],
            fmaf(ga.w, g_state[3 * (size_t)(NCH * NB) + sb],
            fmaf(gb.x, g_state[4 * (size_t)(NCH * NB) + sb],
            fmaf(gb.y, g_state[5 * (size_t)(NCH * NB) + sb], gb.z))))));
    }

    buf[tx * 33 + ty] = y;
    __syncthreads();

    out[(size_t)ty * NS + blockIdx.x * 32 + tx] = buf[ty * 33 + tx];
}

extern "C" void kernel_launch(void* const* d_in, const int* in_sizes, int n_in,
                              void* d_out, int out_size)
{
    const float* x       = (const float*)d_in[0];
    const float* alpha   = (const float*)d_in[1];
    const float* beta    = (const float*)d_in[2];
    const float* low_db  = (const float*)d_in[3];
    const float* mid_db  = (const float*)d_in[4];
    const float* mid_fc  = (const float*)d_in[5];
    const float* mid_Q   = (const float*)d_in[6];
    const float* high_db = (const float*)d_in[7];
    const float* alpha_a = (const float*)d_in[8];
    float* out = (float*)d_out;

    fused_kernel<<<NCH, 64>>>(x, alpha, beta, low_db, mid_db, mid_fc,
                              mid_Q, high_db, alpha_a);
    scan_kernel<<<NB, 384>>>();
    dim3 ob(32, 32);
    out_kernel<<<NS / 32, ob>>>(out);
}